// round 15
// baseline (speedup 1.0000x reference)
#include <cuda_runtime.h>
#include <math.h>

#define NN 100000
#define EE 1600000

// ---- scratch (static device arrays; no runtime allocation) ----
__device__ float g_xl1[(size_t)NN * 128];
__device__ float g_xr1[(size_t)NN * 128];
__device__ float g_h  [(size_t)NN * 128];
__device__ float g_xl2[(size_t)NN * 4];
__device__ float g_xr2[(size_t)NN * 4];
__device__ int   g_cnt[NN];
__device__ int   g_off[NN];
__device__ int   g_cur[NN];
__device__ int   g_esrc[EE];

// ---------------- CSR build: histogram / scan / scatter ----------------
__global__ void zero_kernel(int n) {
    int i = blockIdx.x * blockDim.x + threadIdx.x;
    if (i < n) { g_cnt[i] = 0; g_cur[i] = 0; }
}

__global__ void hist_kernel(const int* __restrict__ dst, int e) {
    int i = blockIdx.x * blockDim.x + threadIdx.x;
    if (i < e) atomicAdd(&g_cnt[dst[i]], 1);
}

__global__ void scan_kernel(int n) {
    __shared__ int tmp[1024];
    int tid = threadIdx.x;
    int per = (n + 1023) >> 10;
    int base = tid * per;
    int sum = 0;
    for (int i = 0; i < per; i++) {
        int j = base + i;
        if (j < n) sum += g_cnt[j];
    }
    tmp[tid] = sum;
    __syncthreads();
    for (int off = 1; off < 1024; off <<= 1) {
        int v = (tid >= off) ? tmp[tid - off] : 0;
        __syncthreads();
        tmp[tid] += v;
        __syncthreads();
    }
    int run = tmp[tid] - sum;  // exclusive prefix
    for (int i = 0; i < per; i++) {
        int j = base + i;
        if (j < n) { g_off[j] = run; run += g_cnt[j]; }
    }
}

__global__ void scatter_kernel(const int* __restrict__ src, const int* __restrict__ dst, int e) {
    int i = blockIdx.x * blockDim.x + threadIdx.x;
    if (i < e) {
        int d = dst[i];
        int p = g_off[d] + atomicAdd(&g_cur[d], 1);
        g_esrc[p] = src[i];
    }
}

// ---------------- GEMM: out[n,128] = A[n,128] @ W[128,128] + bias ----------------
// 128x128 block tile, 8x8 per-thread microtile, 32-k smem stages.
__global__ __launch_bounds__(256) void gemm_nk128(
    const float* __restrict__ A, const float* __restrict__ W,
    const float* __restrict__ bias, float* __restrict__ out, int n)
{
    __shared__ float Ws[32][128];
    __shared__ float As[32][132];   // [k][row], padded row pitch
    int row0 = blockIdx.x * 128;
    int tx = threadIdx.x;
    int cg = tx & 15;              // col group: cols cg*8 .. cg*8+7
    int rg = tx >> 4;              // row group: rows rg*8 .. rg*8+7
    float acc[8][8];
#pragma unroll
    for (int i = 0; i < 8; i++)
#pragma unroll
        for (int j = 0; j < 8; j++) acc[i][j] = 0.f;

    for (int kb = 0; kb < 128; kb += 32) {
        {
            const float4* Wv = (const float4*)(W + (size_t)kb * 128);
            float4* Wsv = (float4*)Ws;
#pragma unroll
            for (int i = 0; i < 4; i++) Wsv[tx + 256 * i] = Wv[tx + 256 * i];
        }
#pragma unroll
        for (int i = 0; i < 4; i++) {
            int idx = tx + 256 * i;        // 0..1023
            int r   = idx >> 3;            // 0..127
            int g4  = (idx & 7) << 2;      // k offset 0..28
            int row = row0 + r;
            float4 v = make_float4(0.f, 0.f, 0.f, 0.f);
            if (row < n) v = *(const float4*)(A + (size_t)row * 128 + kb + g4);
            As[g4 + 0][r] = v.x; As[g4 + 1][r] = v.y;
            As[g4 + 2][r] = v.z; As[g4 + 3][r] = v.w;
        }
        __syncthreads();
#pragma unroll
        for (int k = 0; k < 32; k++) {
            float a[8], w[8];
            *(float4*)&a[0] = *(float4*)&As[k][rg * 8];
            *(float4*)&a[4] = *(float4*)&As[k][rg * 8 + 4];
            *(float4*)&w[0] = *(float4*)&Ws[k][cg * 8];
            *(float4*)&w[4] = *(float4*)&Ws[k][cg * 8 + 4];
#pragma unroll
            for (int i = 0; i < 8; i++)
#pragma unroll
                for (int j = 0; j < 8; j++) acc[i][j] += a[i] * w[j];
        }
        __syncthreads();
    }
    float b[8];
    *(float4*)&b[0] = *(const float4*)(bias + cg * 8);
    *(float4*)&b[4] = *(const float4*)(bias + cg * 8 + 4);
#pragma unroll
    for (int i = 0; i < 8; i++) {
        int row = row0 + rg * 8 + i;
        if (row < n) {
            float4 o0 = make_float4(acc[i][0] + b[0], acc[i][1] + b[1],
                                    acc[i][2] + b[2], acc[i][3] + b[3]);
            float4 o1 = make_float4(acc[i][4] + b[4], acc[i][5] + b[5],
                                    acc[i][6] + b[6], acc[i][7] + b[7]);
            *(float4*)(out + (size_t)row * 128 + cg * 8)     = o0;
            *(float4*)(out + (size_t)row * 128 + cg * 8 + 4) = o1;
        }
    }
}

// ---------------- Layer-1 fused attention (non-centered softmax) ----------------
__device__ __forceinline__ void gat_update_nc(const float4 a, const float4 xr4, const float4 at4,
                                              float& s, float4& acc)
{
    float ex = a.x + xr4.x; ex = ex > 0.f ? ex : 0.2f * ex;
    float ey = a.y + xr4.y; ey = ey > 0.f ? ey : 0.2f * ey;
    float ez = a.z + xr4.z; ez = ez > 0.f ? ez : 0.2f * ez;
    float ew = a.w + xr4.w; ew = ew > 0.f ? ew : 0.2f * ew;
    float p = ex * at4.x + ey * at4.y + ez * at4.z + ew * at4.w;
    p += __shfl_xor_sync(0xffffffffu, p, 1);
    p += __shfl_xor_sync(0xffffffffu, p, 2);
    p += __shfl_xor_sync(0xffffffffu, p, 4);
    float w = __expf(p);
    s += w;
    acc.x += w * a.x;
    acc.y += w * a.y;
    acc.z += w * a.z;
    acc.w += w * a.w;
}

// warp per dst node; lane owns 4 channels; 4-way pipelined edge loop.
__global__ void gat1_kernel(const float* __restrict__ att, const float* __restrict__ bias, int n)
{
    int node = (blockIdx.x * blockDim.x + threadIdx.x) >> 5;
    if (node >= n) return;
    int l = threadIdx.x & 31;   // lane owns channels 4l..4l+3 (head = l>>3)

    const float4 xr4 = *(const float4*)(g_xr1 + (size_t)node * 128 + 4 * l);
    const float4 at4 = *(const float4*)(att + 4 * l);
    int start = g_off[node];
    int cnt   = g_cnt[node];

    float s0 = 0.f; float4 c0 = make_float4(0.f, 0.f, 0.f, 0.f);
    float s1 = 0.f; float4 c1 = make_float4(0.f, 0.f, 0.f, 0.f);
    float s2 = 0.f; float4 c2 = make_float4(0.f, 0.f, 0.f, 0.f);
    float s3 = 0.f; float4 c3 = make_float4(0.f, 0.f, 0.f, 0.f);

    int idxreg = (l < cnt) ? __ldg(&g_esrc[start + l]) : 0;
    int nb = cnt < 32 ? cnt : 32;
    int i = 0;
    for (; i + 4 <= nb; i += 4) {
        int sa = __shfl_sync(0xffffffffu, idxreg, i);
        int sb = __shfl_sync(0xffffffffu, idxreg, i + 1);
        int sc = __shfl_sync(0xffffffffu, idxreg, i + 2);
        int sd = __shfl_sync(0xffffffffu, idxreg, i + 3);
        float4 va = *(const float4*)(g_xl1 + (size_t)sa * 128 + 4 * l);
        float4 vb = *(const float4*)(g_xl1 + (size_t)sb * 128 + 4 * l);
        float4 vc = *(const float4*)(g_xl1 + (size_t)sc * 128 + 4 * l);
        float4 vd = *(const float4*)(g_xl1 + (size_t)sd * 128 + 4 * l);
        gat_update_nc(va, xr4, at4, s0, c0);
        gat_update_nc(vb, xr4, at4, s1, c1);
        gat_update_nc(vc, xr4, at4, s2, c2);
        gat_update_nc(vd, xr4, at4, s3, c3);
    }
    for (; i < cnt; i++) {
        int sa = (i < 32) ? __shfl_sync(0xffffffffu, idxreg, i)
                          : __ldg(&g_esrc[start + i]);
        float4 va = *(const float4*)(g_xl1 + (size_t)sa * 128 + 4 * l);
        gat_update_nc(va, xr4, at4, s0, c0);
    }
    float s = (s0 + s1) + (s2 + s3);
    float4 c;
    c.x = (c0.x + c1.x) + (c2.x + c3.x);
    c.y = (c0.y + c1.y) + (c2.y + c3.y);
    c.z = (c0.z + c1.z) + (c2.z + c3.z);
    c.w = (c0.w + c1.w) + (c2.w + c3.w);

    float inv = (cnt > 0) ? 1.f / s : 0.f;
    float4 b4 = *(const float4*)(bias + 4 * l);
    float4 o;
    o.x = c.x * inv + b4.x;
    o.y = c.y * inv + b4.y;
    o.z = c.z * inv + b4.z;
    o.w = c.w * inv + b4.w;
    o.x = o.x > 0.f ? o.x : (__expf(o.x) - 1.f);
    o.y = o.y > 0.f ? o.y : (__expf(o.y) - 1.f);
    o.z = o.z > 0.f ? o.z : (__expf(o.z) - 1.f);
    o.w = o.w > 0.f ? o.w : (__expf(o.w) - 1.f);
    *(float4*)(g_h + (size_t)node * 128 + 4 * l) = o;
}

// ---------------- Layer-2 linear: xl2/xr2 = h @ W2{l,r} + b2{l,r} ----------------
__global__ void lin2_kernel(const float* __restrict__ W2l, const float* __restrict__ b2l,
                            const float* __restrict__ W2r, const float* __restrict__ b2r, int n)
{
    __shared__ float wl[512], wr[512];
    int tx = threadIdx.x;
    for (int i = tx; i < 512; i += blockDim.x) { wl[i] = W2l[i]; wr[i] = W2r[i]; }
    __syncthreads();
    int node = (blockIdx.x * blockDim.x + tx) >> 5;
    if (node >= n) return;
    int l = tx & 31;
    float hv[4];
    *(float4*)hv = *(const float4*)(g_h + (size_t)node * 128 + 4 * l);
    float pl0 = 0.f, pl1 = 0.f, pl2 = 0.f, pl3 = 0.f;
    float pr0 = 0.f, pr1 = 0.f, pr2 = 0.f, pr3 = 0.f;
#pragma unroll
    for (int j = 0; j < 4; j++) {
        int k = 4 * l + j;
        float a = hv[j];
        pl0 += a * wl[k * 4 + 0]; pl1 += a * wl[k * 4 + 1];
        pl2 += a * wl[k * 4 + 2]; pl3 += a * wl[k * 4 + 3];
        pr0 += a * wr[k * 4 + 0]; pr1 += a * wr[k * 4 + 1];
        pr2 += a * wr[k * 4 + 2]; pr3 += a * wr[k * 4 + 3];
    }
#pragma unroll
    for (int off = 16; off; off >>= 1) {
        pl0 += __shfl_xor_sync(0xffffffffu, pl0, off);
        pl1 += __shfl_xor_sync(0xffffffffu, pl1, off);
        pl2 += __shfl_xor_sync(0xffffffffu, pl2, off);
        pl3 += __shfl_xor_sync(0xffffffffu, pl3, off);
        pr0 += __shfl_xor_sync(0xffffffffu, pr0, off);
        pr1 += __shfl_xor_sync(0xffffffffu, pr1, off);
        pr2 += __shfl_xor_sync(0xffffffffu, pr2, off);
        pr3 += __shfl_xor_sync(0xffffffffu, pr3, off);
    }
    if (l == 0) {
        float4 ol  = make_float4(pl0 + b2l[0], pl1 + b2l[1], pl2 + b2l[2], pl3 + b2l[3]);
        float4 orr = make_float4(pr0 + b2r[0], pr1 + b2r[1], pr2 + b2r[2], pr3 + b2r[3]);
        *(float4*)(g_xl2 + (size_t)node * 4) = ol;
        *(float4*)(g_xr2 + (size_t)node * 4) = orr;
    }
}

// ---------------- Layer-2 fused attention (non-centered softmax) ----------------
__global__ void gat2_kernel(const float* __restrict__ att2, const float* __restrict__ bias2,
                            float* __restrict__ out, int n)
{
    int node = (blockIdx.x * blockDim.x + threadIdx.x) >> 5;
    if (node >= n) return;
    int l = threadIdx.x & 31;
    float xr[4]; *(float4*)xr = *(const float4*)(g_xr2 + (size_t)node * 4);
    float at[4]; *(float4*)at = *(const float4*)att2;
    float s = 0.f, a0 = 0.f, a1 = 0.f, a2 = 0.f, a3 = 0.f;
    int start = g_off[node];
    int cnt   = g_cnt[node];

    for (int i = l; i < cnt; i += 32) {
        int src = __ldg(&g_esrc[start + i]);
        float v[4]; *(float4*)v = *(const float4*)(g_xl2 + (size_t)src * 4);
        float e0 = v[0] + xr[0]; e0 = e0 > 0.f ? e0 : 0.2f * e0;
        float e1 = v[1] + xr[1]; e1 = e1 > 0.f ? e1 : 0.2f * e1;
        float e2 = v[2] + xr[2]; e2 = e2 > 0.f ? e2 : 0.2f * e2;
        float e3 = v[3] + xr[3]; e3 = e3 > 0.f ? e3 : 0.2f * e3;
        float p = e0 * at[0] + e1 * at[1] + e2 * at[2] + e3 * at[3];
        float w = __expf(p);
        s  += w;
        a0 += w * v[0];
        a1 += w * v[1];
        a2 += w * v[2];
        a3 += w * v[3];
    }
#pragma unroll
    for (int off = 16; off; off >>= 1) {
        s  += __shfl_xor_sync(0xffffffffu, s, off);
        a0 += __shfl_xor_sync(0xffffffffu, a0, off);
        a1 += __shfl_xor_sync(0xffffffffu, a1, off);
        a2 += __shfl_xor_sync(0xffffffffu, a2, off);
        a3 += __shfl_xor_sync(0xffffffffu, a3, off);
    }
    if (l == 0) {
        float inv = (cnt > 0) ? 1.f / s : 0.f;
        float4 o = make_float4(a0 * inv + bias2[0], a1 * inv + bias2[1],
                               a2 * inv + bias2[2], a3 * inv + bias2[3]);
        *(float4*)(out + (size_t)node * 4) = o;
    }
}

// ---------------- host launcher ----------------
extern "C" void kernel_launch(void* const* d_in, const int* in_sizes, int n_in,
                              void* d_out, int out_size)
{
    const float* x     = (const float*)d_in[0];
    const int*   ei    = (const int*)  d_in[1];
    const float* W1l   = (const float*)d_in[2];
    const float* b1l   = (const float*)d_in[3];
    const float* W1r   = (const float*)d_in[4];
    const float* b1r   = (const float*)d_in[5];
    const float* att1  = (const float*)d_in[6];
    const float* bias1 = (const float*)d_in[7];
    const float* W2l   = (const float*)d_in[8];
    const float* b2l   = (const float*)d_in[9];
    const float* W2r   = (const float*)d_in[10];
    const float* b2r   = (const float*)d_in[11];
    const float* att2  = (const float*)d_in[12];
    const float* bias2 = (const float*)d_in[13];
    float* out = (float*)d_out;

    int n = in_sizes[0] / 128;
    int e = in_sizes[1] / 2;
    const int* src = ei;
    const int* dst = ei + e;

    void *p_xl1, *p_xr1;
    cudaGetSymbolAddress(&p_xl1, g_xl1);
    cudaGetSymbolAddress(&p_xr1, g_xr1);

    static cudaStream_t s1 = nullptr;
    static cudaEvent_t ev_fork = nullptr, ev_join = nullptr;
    if (!s1) {
        cudaStreamCreateWithFlags(&s1, cudaStreamNonBlocking);
        cudaEventCreateWithFlags(&ev_fork, cudaEventDisableTiming);
        cudaEventCreateWithFlags(&ev_join, cudaEventDisableTiming);
    }

    // fork: CSR build on s1, GEMMs on the main (captured) stream
    cudaEventRecord(ev_fork, 0);
    cudaStreamWaitEvent(s1, ev_fork, 0);

    zero_kernel   <<<(n + 255) / 256, 256, 0, s1>>>(n);
    hist_kernel   <<<(e + 255) / 256, 256, 0, s1>>>(dst, e);
    scan_kernel   <<<1, 1024, 0, s1>>>(n);
    scatter_kernel<<<(e + 255) / 256, 256, 0, s1>>>(src, dst, e);
    cudaEventRecord(ev_join, s1);

    gemm_nk128<<<(n + 127) / 128, 256>>>(x, W1l, b1l, (float*)p_xl1, n);
    gemm_nk128<<<(n + 127) / 128, 256>>>(x, W1r, b1r, (float*)p_xr1, n);

    // join: gat1 needs both GEMM outputs and the CSR
    cudaStreamWaitEvent(0, ev_join, 0);

    gat1_kernel<<<(n + 7) / 8, 256>>>(att1, bias1, n);
    lin2_kernel<<<(n + 7) / 8, 256>>>(W2l, b2l, W2r, b2r, n);
    gat2_kernel<<<(n + 7) / 8, 256>>>(att2, bias2, out, n);
}

// round 16
// speedup vs baseline: 1.0491x; 1.0491x over previous
#include <cuda_runtime.h>
#include <cuda_fp16.h>
#include <math.h>
#include <stdint.h>

#define NN 100000
#define EE 1600000

// ---- scratch (static device arrays; no runtime allocation) ----
__device__ float g_xl1[(size_t)NN * 128];
__device__ float g_xr1[(size_t)NN * 128];
__device__ float g_h  [(size_t)NN * 128];
__device__ float g_xl2[(size_t)NN * 4];
__device__ float g_xr2[(size_t)NN * 4];
__device__ int   g_cnt[NN];
__device__ int   g_off[NN];
__device__ int   g_cur[NN];
__device__ int   g_esrc[EE];

// ---------------- CSR build: histogram / scan / scatter ----------------
__global__ void zero_kernel(int n) {
    int i = blockIdx.x * blockDim.x + threadIdx.x;
    if (i < n) { g_cnt[i] = 0; g_cur[i] = 0; }
}

__global__ void hist_kernel(const int* __restrict__ dst, int e) {
    int i = blockIdx.x * blockDim.x + threadIdx.x;
    if (i < e) atomicAdd(&g_cnt[dst[i]], 1);
}

__global__ void scan_kernel(int n) {
    __shared__ int tmp[1024];
    int tid = threadIdx.x;
    int per = (n + 1023) >> 10;
    int base = tid * per;
    int sum = 0;
    for (int i = 0; i < per; i++) {
        int j = base + i;
        if (j < n) sum += g_cnt[j];
    }
    tmp[tid] = sum;
    __syncthreads();
    for (int off = 1; off < 1024; off <<= 1) {
        int v = (tid >= off) ? tmp[tid - off] : 0;
        __syncthreads();
        tmp[tid] += v;
        __syncthreads();
    }
    int run = tmp[tid] - sum;  // exclusive prefix
    for (int i = 0; i < per; i++) {
        int j = base + i;
        if (j < n) { g_off[j] = run; run += g_cnt[j]; }
    }
}

__global__ void scatter_kernel(const int* __restrict__ src, const int* __restrict__ dst, int e) {
    int i = blockIdx.x * blockDim.x + threadIdx.x;
    if (i < e) {
        int d = dst[i];
        int p = g_off[d] + atomicAdd(&g_cur[d], 1);
        g_esrc[p] = src[i];
    }
}

// ---------------- GEMM via HFMA2: out[n,128] = A[n,128] @ W[128,128] + bias ----------------
// 128x128 block tile, 8x8 per-thread microtile. Inputs rounded to fp16;
// A pre-duplicated as half2 in smem; half2 accumulators drained to fp32 every 16 k.
__global__ __launch_bounds__(256) void gemm_h2(
    const float* __restrict__ A, const float* __restrict__ W,
    const float* __restrict__ bias, float* __restrict__ out, int n)
{
    __shared__ uint32_t Ash[32][132];  // dup-half2(a,a), [k][row]
    __shared__ uint32_t Wsh[32][68];   // half2(w[2j],w[2j+1]), [k][j]
    int row0 = blockIdx.x * 128;
    int tx = threadIdx.x;
    int cg = tx & 15;              // col group: cols cg*8 .. cg*8+7
    int rg = tx >> 4;              // row group: rows rg*8 .. rg*8+7

    uint32_t acch[8][4];           // half2 partial accumulators
    float    accf[8][8];           // fp32 master accumulators
#pragma unroll
    for (int i = 0; i < 8; i++) {
#pragma unroll
        for (int j = 0; j < 4; j++) acch[i][j] = 0u;
#pragma unroll
        for (int j = 0; j < 8; j++) accf[i][j] = 0.f;
    }

    for (int kb = 0; kb < 128; kb += 32) {
#pragma unroll
        for (int i = 0; i < 4; i++) {
            int idx = tx + 256 * i;
            int k   = idx >> 5;
            int c4  = (idx & 31) << 2;
            float4 v = *(const float4*)(W + (size_t)(kb + k) * 128 + c4);
            __half2 h0 = __floats2half2_rn(v.x, v.y);
            __half2 h1 = __floats2half2_rn(v.z, v.w);
            Wsh[k][(c4 >> 1)]     = *(uint32_t*)&h0;
            Wsh[k][(c4 >> 1) + 1] = *(uint32_t*)&h1;
        }
#pragma unroll
        for (int i = 0; i < 4; i++) {
            int idx = tx + 256 * i;
            int r   = idx >> 3;
            int g4  = (idx & 7) << 2;
            int row = row0 + r;
            float4 v = make_float4(0.f, 0.f, 0.f, 0.f);
            if (row < n) v = *(const float4*)(A + (size_t)row * 128 + kb + g4);
            __half hx = __float2half_rn(v.x), hy = __float2half_rn(v.y);
            __half hz = __float2half_rn(v.z), hw = __float2half_rn(v.w);
            __half2 dx = __half2half2(hx), dy = __half2half2(hy);
            __half2 dz = __half2half2(hz), dw = __half2half2(hw);
            Ash[g4 + 0][r] = *(uint32_t*)&dx;
            Ash[g4 + 1][r] = *(uint32_t*)&dy;
            Ash[g4 + 2][r] = *(uint32_t*)&dz;
            Ash[g4 + 3][r] = *(uint32_t*)&dw;
        }
        __syncthreads();

#pragma unroll
        for (int kc = 0; kc < 2; kc++) {
#pragma unroll
            for (int k = 0; k < 16; k++) {
                int kk = kc * 16 + k;
                uint32_t a[8], w[4];
                *(uint4*)&a[0] = *(uint4*)&Ash[kk][rg * 8];
                *(uint4*)&a[4] = *(uint4*)&Ash[kk][rg * 8 + 4];
                *(uint4*)&w[0] = *(uint4*)&Wsh[kk][cg * 4];
#pragma unroll
                for (int i = 0; i < 8; i++)
#pragma unroll
                    for (int j = 0; j < 4; j++)
                        asm("fma.rn.f16x2 %0, %1, %2, %0;"
                            : "+r"(acch[i][j]) : "r"(a[i]), "r"(w[j]));
            }
#pragma unroll
            for (int i = 0; i < 8; i++)
#pragma unroll
                for (int j = 0; j < 4; j++) {
                    float2 f = __half22float2(*(__half2*)&acch[i][j]);
                    accf[i][2 * j]     += f.x;
                    accf[i][2 * j + 1] += f.y;
                    acch[i][j] = 0u;
                }
        }
        __syncthreads();
    }

    float b[8];
    *(float4*)&b[0] = *(const float4*)(bias + cg * 8);
    *(float4*)&b[4] = *(const float4*)(bias + cg * 8 + 4);
#pragma unroll
    for (int i = 0; i < 8; i++) {
        int row = row0 + rg * 8 + i;
        if (row < n) {
            float4 o0 = make_float4(accf[i][0] + b[0], accf[i][1] + b[1],
                                    accf[i][2] + b[2], accf[i][3] + b[3]);
            float4 o1 = make_float4(accf[i][4] + b[4], accf[i][5] + b[5],
                                    accf[i][6] + b[6], accf[i][7] + b[7]);
            *(float4*)(out + (size_t)row * 128 + cg * 8)     = o0;
            *(float4*)(out + (size_t)row * 128 + cg * 8 + 4) = o1;
        }
    }
}

// ---------------- Layer-1 fused attention (non-centered softmax) ----------------
__device__ __forceinline__ void gat_update_nc(const float4 a, const float4 xr4, const float4 at4,
                                              float& s, float4& acc)
{
    float ex = a.x + xr4.x; ex = ex > 0.f ? ex : 0.2f * ex;
    float ey = a.y + xr4.y; ey = ey > 0.f ? ey : 0.2f * ey;
    float ez = a.z + xr4.z; ez = ez > 0.f ? ez : 0.2f * ez;
    float ew = a.w + xr4.w; ew = ew > 0.f ? ew : 0.2f * ew;
    float p = ex * at4.x + ey * at4.y + ez * at4.z + ew * at4.w;
    p += __shfl_xor_sync(0xffffffffu, p, 1);
    p += __shfl_xor_sync(0xffffffffu, p, 2);
    p += __shfl_xor_sync(0xffffffffu, p, 4);
    float w = __expf(p);
    s += w;
    acc.x += w * a.x;
    acc.y += w * a.y;
    acc.z += w * a.z;
    acc.w += w * a.w;
}

// warp per dst node; lane owns 4 channels; 4-way pipelined edge loop. (R6 exact)
__global__ void gat1_kernel(const float* __restrict__ att, const float* __restrict__ bias, int n)
{
    int node = (blockIdx.x * blockDim.x + threadIdx.x) >> 5;
    if (node >= n) return;
    int l = threadIdx.x & 31;

    const float4 xr4 = *(const float4*)(g_xr1 + (size_t)node * 128 + 4 * l);
    const float4 at4 = *(const float4*)(att + 4 * l);
    int start = g_off[node];
    int cnt   = g_cnt[node];

    float s0 = 0.f; float4 c0 = make_float4(0.f, 0.f, 0.f, 0.f);
    float s1 = 0.f; float4 c1 = make_float4(0.f, 0.f, 0.f, 0.f);
    float s2 = 0.f; float4 c2 = make_float4(0.f, 0.f, 0.f, 0.f);
    float s3 = 0.f; float4 c3 = make_float4(0.f, 0.f, 0.f, 0.f);

    int idxreg = (l < cnt) ? __ldg(&g_esrc[start + l]) : 0;
    int nb = cnt < 32 ? cnt : 32;
    int i = 0;
    for (; i + 4 <= nb; i += 4) {
        int sa = __shfl_sync(0xffffffffu, idxreg, i);
        int sb = __shfl_sync(0xffffffffu, idxreg, i + 1);
        int sc = __shfl_sync(0xffffffffu, idxreg, i + 2);
        int sd = __shfl_sync(0xffffffffu, idxreg, i + 3);
        float4 va = *(const float4*)(g_xl1 + (size_t)sa * 128 + 4 * l);
        float4 vb = *(const float4*)(g_xl1 + (size_t)sb * 128 + 4 * l);
        float4 vc = *(const float4*)(g_xl1 + (size_t)sc * 128 + 4 * l);
        float4 vd = *(const float4*)(g_xl1 + (size_t)sd * 128 + 4 * l);
        gat_update_nc(va, xr4, at4, s0, c0);
        gat_update_nc(vb, xr4, at4, s1, c1);
        gat_update_nc(vc, xr4, at4, s2, c2);
        gat_update_nc(vd, xr4, at4, s3, c3);
    }
    for (; i < cnt; i++) {
        int sa = (i < 32) ? __shfl_sync(0xffffffffu, idxreg, i)
                          : __ldg(&g_esrc[start + i]);
        float4 va = *(const float4*)(g_xl1 + (size_t)sa * 128 + 4 * l);
        gat_update_nc(va, xr4, at4, s0, c0);
    }
    float s = (s0 + s1) + (s2 + s3);
    float4 c;
    c.x = (c0.x + c1.x) + (c2.x + c3.x);
    c.y = (c0.y + c1.y) + (c2.y + c3.y);
    c.z = (c0.z + c1.z) + (c2.z + c3.z);
    c.w = (c0.w + c1.w) + (c2.w + c3.w);

    float inv = (cnt > 0) ? 1.f / s : 0.f;
    float4 b4 = *(const float4*)(bias + 4 * l);
    float4 o;
    o.x = c.x * inv + b4.x;
    o.y = c.y * inv + b4.y;
    o.z = c.z * inv + b4.z;
    o.w = c.w * inv + b4.w;
    o.x = o.x > 0.f ? o.x : (__expf(o.x) - 1.f);
    o.y = o.y > 0.f ? o.y : (__expf(o.y) - 1.f);
    o.z = o.z > 0.f ? o.z : (__expf(o.z) - 1.f);
    o.w = o.w > 0.f ? o.w : (__expf(o.w) - 1.f);
    *(float4*)(g_h + (size_t)node * 128 + 4 * l) = o;
}

// ---------------- Layer-2 linear: xl2/xr2 = h @ W2{l,r} + b2{l,r} ---------------- (R6 exact)
__global__ void lin2_kernel(const float* __restrict__ W2l, const float* __restrict__ b2l,
                            const float* __restrict__ W2r, const float* __restrict__ b2r, int n)
{
    __shared__ float wl[512], wr[512];
    int tx = threadIdx.x;
    for (int i = tx; i < 512; i += blockDim.x) { wl[i] = W2l[i]; wr[i] = W2r[i]; }
    __syncthreads();
    int node = (blockIdx.x * blockDim.x + tx) >> 5;
    if (node >= n) return;
    int l = tx & 31;
    float hv[4];
    *(float4*)hv = *(const float4*)(g_h + (size_t)node * 128 + 4 * l);
    float pl0 = 0.f, pl1 = 0.f, pl2 = 0.f, pl3 = 0.f;
    float pr0 = 0.f, pr1 = 0.f, pr2 = 0.f, pr3 = 0.f;
#pragma unroll
    for (int j = 0; j < 4; j++) {
        int k = 4 * l + j;
        float a = hv[j];
        pl0 += a * wl[k * 4 + 0]; pl1 += a * wl[k * 4 + 1];
        pl2 += a * wl[k * 4 + 2]; pl3 += a * wl[k * 4 + 3];
        pr0 += a * wr[k * 4 + 0]; pr1 += a * wr[k * 4 + 1];
        pr2 += a * wr[k * 4 + 2]; pr3 += a * wr[k * 4 + 3];
    }
#pragma unroll
    for (int off = 16; off; off >>= 1) {
        pl0 += __shfl_xor_sync(0xffffffffu, pl0, off);
        pl1 += __shfl_xor_sync(0xffffffffu, pl1, off);
        pl2 += __shfl_xor_sync(0xffffffffu, pl2, off);
        pl3 += __shfl_xor_sync(0xffffffffu, pl3, off);
        pr0 += __shfl_xor_sync(0xffffffffu, pr0, off);
        pr1 += __shfl_xor_sync(0xffffffffu, pr1, off);
        pr2 += __shfl_xor_sync(0xffffffffu, pr2, off);
        pr3 += __shfl_xor_sync(0xffffffffu, pr3, off);
    }
    if (l == 0) {
        float4 ol  = make_float4(pl0 + b2l[0], pl1 + b2l[1], pl2 + b2l[2], pl3 + b2l[3]);
        float4 orr = make_float4(pr0 + b2r[0], pr1 + b2r[1], pr2 + b2r[2], pr3 + b2r[3]);
        *(float4*)(g_xl2 + (size_t)node * 4) = ol;
        *(float4*)(g_xr2 + (size_t)node * 4) = orr;
    }
}

// ---------------- Layer-2 fused attention: TWO nodes per warp (16 lanes each) ----------------
__global__ void gat2_kernel(const float* __restrict__ att2, const float* __restrict__ bias2,
                            float* __restrict__ out, int n)
{
    int warp = (blockIdx.x * blockDim.x + threadIdx.x) >> 5;
    int l   = threadIdx.x & 31;
    int sub = l >> 4;           // which node in the pair
    int sl  = l & 15;           // lane within the 16-lane group
    int node_raw = warp * 2 + sub;
    if (warp * 2 >= n) return;
    int node = node_raw < n ? node_raw : n - 1;   // clamp (store predicated below)

    float xr[4]; *(float4*)xr = *(const float4*)(g_xr2 + (size_t)node * 4);
    float at[4]; *(float4*)at = *(const float4*)att2;
    float s = 0.f, a0 = 0.f, a1 = 0.f, a2 = 0.f, a3 = 0.f;
    int start = g_off[node];
    int cnt   = g_cnt[node];

    for (int i = sl; i < cnt; i += 16) {
        int src = __ldg(&g_esrc[start + i]);
        float v[4]; *(float4*)v = *(const float4*)(g_xl2 + (size_t)src * 4);
        float e0 = v[0] + xr[0]; e0 = e0 > 0.f ? e0 : 0.2f * e0;
        float e1 = v[1] + xr[1]; e1 = e1 > 0.f ? e1 : 0.2f * e1;
        float e2 = v[2] + xr[2]; e2 = e2 > 0.f ? e2 : 0.2f * e2;
        float e3 = v[3] + xr[3]; e3 = e3 > 0.f ? e3 : 0.2f * e3;
        float p = e0 * at[0] + e1 * at[1] + e2 * at[2] + e3 * at[3];
        float w = __expf(p);
        s  += w;
        a0 += w * v[0];
        a1 += w * v[1];
        a2 += w * v[2];
        a3 += w * v[3];
    }
    // merge within each 16-lane group (xor offsets never set bit 4)
#pragma unroll
    for (int off = 8; off; off >>= 1) {
        s  += __shfl_xor_sync(0xffffffffu, s, off);
        a0 += __shfl_xor_sync(0xffffffffu, a0, off);
        a1 += __shfl_xor_sync(0xffffffffu, a1, off);
        a2 += __shfl_xor_sync(0xffffffffu, a2, off);
        a3 += __shfl_xor_sync(0xffffffffu, a3, off);
    }
    if (sl == 0 && node_raw < n) {
        float inv = (cnt > 0) ? 1.f / s : 0.f;
        float4 o = make_float4(a0 * inv + bias2[0], a1 * inv + bias2[1],
                               a2 * inv + bias2[2], a3 * inv + bias2[3]);
        *(float4*)(out + (size_t)node * 4) = o;
    }
}

// ---------------- host launcher ----------------
extern "C" void kernel_launch(void* const* d_in, const int* in_sizes, int n_in,
                              void* d_out, int out_size)
{
    const float* x     = (const float*)d_in[0];
    const int*   ei    = (const int*)  d_in[1];
    const float* W1l   = (const float*)d_in[2];
    const float* b1l   = (const float*)d_in[3];
    const float* W1r   = (const float*)d_in[4];
    const float* b1r   = (const float*)d_in[5];
    const float* att1  = (const float*)d_in[6];
    const float* bias1 = (const float*)d_in[7];
    const float* W2l   = (const float*)d_in[8];
    const float* b2l   = (const float*)d_in[9];
    const float* W2r   = (const float*)d_in[10];
    const float* b2r   = (const float*)d_in[11];
    const float* att2  = (const float*)d_in[12];
    const float* bias2 = (const float*)d_in[13];
    float* out = (float*)d_out;

    int n = in_sizes[0] / 128;
    int e = in_sizes[1] / 2;
    const int* src = ei;
    const int* dst = ei + e;

    void *p_xl1, *p_xr1;
    cudaGetSymbolAddress(&p_xl1, g_xl1);
    cudaGetSymbolAddress(&p_xr1, g_xr1);

    static cudaStream_t s1 = nullptr;
    static cudaEvent_t ev_fork = nullptr, ev_join = nullptr;
    if (!s1) {
        cudaStreamCreateWithFlags(&s1, cudaStreamNonBlocking);
        cudaEventCreateWithFlags(&ev_fork, cudaEventDisableTiming);
        cudaEventCreateWithFlags(&ev_join, cudaEventDisableTiming);
    }

    // fork: CSR build on s1, GEMMs on the main (captured) stream
    cudaEventRecord(ev_fork, 0);
    cudaStreamWaitEvent(s1, ev_fork, 0);

    zero_kernel   <<<(n + 255) / 256, 256, 0, s1>>>(n);
    hist_kernel   <<<(e + 255) / 256, 256, 0, s1>>>(dst, e);
    scan_kernel   <<<1, 1024, 0, s1>>>(n);
    scatter_kernel<<<(e + 255) / 256, 256, 0, s1>>>(src, dst, e);
    cudaEventRecord(ev_join, s1);

    gemm_h2<<<(n + 127) / 128, 256>>>(x, W1l, b1l, (float*)p_xl1, n);
    gemm_h2<<<(n + 127) / 128, 256>>>(x, W1r, b1r, (float*)p_xr1, n);

    // join: gat1 needs both GEMM outputs and the CSR
    cudaStreamWaitEvent(0, ev_join, 0);

    gat1_kernel<<<(n + 7) / 8, 256>>>(att1, bias1, n);
    lin2_kernel<<<(n + 7) / 8, 256>>>(W2l, b2l, W2r, b2r, n);
    // two nodes per warp -> 16 nodes per 256-thread block
    gat2_kernel<<<(n + 15) / 16, 256>>>(att2, bias2, out, n);
}

// round 17
// speedup vs baseline: 1.0537x; 1.0043x over previous
#include <cuda_runtime.h>
#include <cuda_fp16.h>
#include <math.h>
#include <stdint.h>

#define NN 100000
#define EE 1600000

// ---- scratch (static device arrays; no runtime allocation) ----
__device__ float g_xl1[(size_t)NN * 128];
__device__ float g_xr1[(size_t)NN * 128];
__device__ float g_h  [(size_t)NN * 128];
__device__ float g_xl2[(size_t)NN * 4];
__device__ float g_xr2[(size_t)NN * 4];
__device__ int   g_cnt[NN];
__device__ int   g_off[NN];
__device__ int   g_cur[NN];
__device__ int   g_esrc[EE];

// ---------------- CSR build: histogram / scan / scatter ----------------
__global__ void zero_kernel(int n) {
    int i = blockIdx.x * blockDim.x + threadIdx.x;
    if (i < n) { g_cnt[i] = 0; g_cur[i] = 0; }
}

__global__ void hist_kernel(const int* __restrict__ dst, int e) {
    int i = blockIdx.x * blockDim.x + threadIdx.x;
    if (i < e) atomicAdd(&g_cnt[dst[i]], 1);
}

__global__ void scan_kernel(int n) {
    __shared__ int tmp[1024];
    int tid = threadIdx.x;
    int per = (n + 1023) >> 10;
    int base = tid * per;
    int sum = 0;
    for (int i = 0; i < per; i++) {
        int j = base + i;
        if (j < n) sum += g_cnt[j];
    }
    tmp[tid] = sum;
    __syncthreads();
    for (int off = 1; off < 1024; off <<= 1) {
        int v = (tid >= off) ? tmp[tid - off] : 0;
        __syncthreads();
        tmp[tid] += v;
        __syncthreads();
    }
    int run = tmp[tid] - sum;  // exclusive prefix
    for (int i = 0; i < per; i++) {
        int j = base + i;
        if (j < n) { g_off[j] = run; run += g_cnt[j]; }
    }
}

__global__ void scatter_kernel(const int* __restrict__ src, const int* __restrict__ dst, int e) {
    int i = blockIdx.x * blockDim.x + threadIdx.x;
    if (i < e) {
        int d = dst[i];
        int p = g_off[d] + atomicAdd(&g_cur[d], 1);
        g_esrc[p] = src[i];
    }
}

// ---------------- GEMM via HFMA2: out[n,128] = A[n,128] @ W[128,128] + bias ----------------
// 128x128 block tile, 8x8 per-thread microtile. Inputs rounded to fp16;
// A pre-duplicated as half2 in smem; half2 accumulators drained to fp32 every 16 k.
__global__ __launch_bounds__(256) void gemm_h2(
    const float* __restrict__ A, const float* __restrict__ W,
    const float* __restrict__ bias, float* __restrict__ out, int n)
{
    __shared__ uint32_t Ash[32][132];  // dup-half2(a,a), [k][row]
    __shared__ uint32_t Wsh[32][68];   // half2(w[2j],w[2j+1]), [k][j]
    int row0 = blockIdx.x * 128;
    int tx = threadIdx.x;
    int cg = tx & 15;              // col group: cols cg*8 .. cg*8+7
    int rg = tx >> 4;              // row group: rows rg*8 .. rg*8+7

    uint32_t acch[8][4];           // half2 partial accumulators
    float    accf[8][8];           // fp32 master accumulators
#pragma unroll
    for (int i = 0; i < 8; i++) {
#pragma unroll
        for (int j = 0; j < 4; j++) acch[i][j] = 0u;
#pragma unroll
        for (int j = 0; j < 8; j++) accf[i][j] = 0.f;
    }

    for (int kb = 0; kb < 128; kb += 32) {
#pragma unroll
        for (int i = 0; i < 4; i++) {
            int idx = tx + 256 * i;
            int k   = idx >> 5;
            int c4  = (idx & 31) << 2;
            float4 v = *(const float4*)(W + (size_t)(kb + k) * 128 + c4);
            __half2 h0 = __floats2half2_rn(v.x, v.y);
            __half2 h1 = __floats2half2_rn(v.z, v.w);
            Wsh[k][(c4 >> 1)]     = *(uint32_t*)&h0;
            Wsh[k][(c4 >> 1) + 1] = *(uint32_t*)&h1;
        }
#pragma unroll
        for (int i = 0; i < 4; i++) {
            int idx = tx + 256 * i;
            int r   = idx >> 3;
            int g4  = (idx & 7) << 2;
            int row = row0 + r;
            float4 v = make_float4(0.f, 0.f, 0.f, 0.f);
            if (row < n) v = *(const float4*)(A + (size_t)row * 128 + kb + g4);
            __half hx = __float2half_rn(v.x), hy = __float2half_rn(v.y);
            __half hz = __float2half_rn(v.z), hw = __float2half_rn(v.w);
            __half2 dx = __half2half2(hx), dy = __half2half2(hy);
            __half2 dz = __half2half2(hz), dw = __half2half2(hw);
            Ash[g4 + 0][r] = *(uint32_t*)&dx;
            Ash[g4 + 1][r] = *(uint32_t*)&dy;
            Ash[g4 + 2][r] = *(uint32_t*)&dz;
            Ash[g4 + 3][r] = *(uint32_t*)&dw;
        }
        __syncthreads();

#pragma unroll
        for (int kc = 0; kc < 2; kc++) {
#pragma unroll
            for (int k = 0; k < 16; k++) {
                int kk = kc * 16 + k;
                uint32_t a[8], w[4];
                *(uint4*)&a[0] = *(uint4*)&Ash[kk][rg * 8];
                *(uint4*)&a[4] = *(uint4*)&Ash[kk][rg * 8 + 4];
                *(uint4*)&w[0] = *(uint4*)&Wsh[kk][cg * 4];
#pragma unroll
                for (int i = 0; i < 8; i++)
#pragma unroll
                    for (int j = 0; j < 4; j++)
                        asm("fma.rn.f16x2 %0, %1, %2, %0;"
                            : "+r"(acch[i][j]) : "r"(a[i]), "r"(w[j]));
            }
#pragma unroll
            for (int i = 0; i < 8; i++)
#pragma unroll
                for (int j = 0; j < 4; j++) {
                    float2 f = __half22float2(*(__half2*)&acch[i][j]);
                    accf[i][2 * j]     += f.x;
                    accf[i][2 * j + 1] += f.y;
                    acch[i][j] = 0u;
                }
        }
        __syncthreads();
    }

    float b[8];
    *(float4*)&b[0] = *(const float4*)(bias + cg * 8);
    *(float4*)&b[4] = *(const float4*)(bias + cg * 8 + 4);
#pragma unroll
    for (int i = 0; i < 8; i++) {
        int row = row0 + rg * 8 + i;
        if (row < n) {
            float4 o0 = make_float4(accf[i][0] + b[0], accf[i][1] + b[1],
                                    accf[i][2] + b[2], accf[i][3] + b[3]);
            float4 o1 = make_float4(accf[i][4] + b[4], accf[i][5] + b[5],
                                    accf[i][6] + b[6], accf[i][7] + b[7]);
            *(float4*)(out + (size_t)row * 128 + cg * 8)     = o0;
            *(float4*)(out + (size_t)row * 128 + cg * 8 + 4) = o1;
        }
    }
}

// ---------------- Layer-1 fused attention (non-centered softmax) ----------------
__device__ __forceinline__ void gat_update_nc(const float4 a, const float4 xr4, const float4 at4,
                                              float& s, float4& acc)
{
    float ex = a.x + xr4.x; ex = ex > 0.f ? ex : 0.2f * ex;
    float ey = a.y + xr4.y; ey = ey > 0.f ? ey : 0.2f * ey;
    float ez = a.z + xr4.z; ez = ez > 0.f ? ez : 0.2f * ez;
    float ew = a.w + xr4.w; ew = ew > 0.f ? ew : 0.2f * ew;
    float p = ex * at4.x + ey * at4.y + ez * at4.z + ew * at4.w;
    p += __shfl_xor_sync(0xffffffffu, p, 1);
    p += __shfl_xor_sync(0xffffffffu, p, 2);
    p += __shfl_xor_sync(0xffffffffu, p, 4);
    float w = __expf(p);
    s += w;
    acc.x += w * a.x;
    acc.y += w * a.y;
    acc.z += w * a.z;
    acc.w += w * a.w;
}

// warp per dst node; lane owns 4 channels; 4-way pipelined edge loop.
__global__ void gat1_kernel(const float* __restrict__ att, const float* __restrict__ bias, int n)
{
    int node = (blockIdx.x * blockDim.x + threadIdx.x) >> 5;
    if (node >= n) return;
    int l = threadIdx.x & 31;

    const float4 xr4 = *(const float4*)(g_xr1 + (size_t)node * 128 + 4 * l);
    const float4 at4 = *(const float4*)(att + 4 * l);
    int start = g_off[node];
    int cnt   = g_cnt[node];

    float s0 = 0.f; float4 c0 = make_float4(0.f, 0.f, 0.f, 0.f);
    float s1 = 0.f; float4 c1 = make_float4(0.f, 0.f, 0.f, 0.f);
    float s2 = 0.f; float4 c2 = make_float4(0.f, 0.f, 0.f, 0.f);
    float s3 = 0.f; float4 c3 = make_float4(0.f, 0.f, 0.f, 0.f);

    int idxreg = (l < cnt) ? __ldg(&g_esrc[start + l]) : 0;
    int nb = cnt < 32 ? cnt : 32;
    int i = 0;
    for (; i + 4 <= nb; i += 4) {
        int sa = __shfl_sync(0xffffffffu, idxreg, i);
        int sb = __shfl_sync(0xffffffffu, idxreg, i + 1);
        int sc = __shfl_sync(0xffffffffu, idxreg, i + 2);
        int sd = __shfl_sync(0xffffffffu, idxreg, i + 3);
        float4 va = *(const float4*)(g_xl1 + (size_t)sa * 128 + 4 * l);
        float4 vb = *(const float4*)(g_xl1 + (size_t)sb * 128 + 4 * l);
        float4 vc = *(const float4*)(g_xl1 + (size_t)sc * 128 + 4 * l);
        float4 vd = *(const float4*)(g_xl1 + (size_t)sd * 128 + 4 * l);
        gat_update_nc(va, xr4, at4, s0, c0);
        gat_update_nc(vb, xr4, at4, s1, c1);
        gat_update_nc(vc, xr4, at4, s2, c2);
        gat_update_nc(vd, xr4, at4, s3, c3);
    }
    for (; i < cnt; i++) {
        int sa = (i < 32) ? __shfl_sync(0xffffffffu, idxreg, i)
                          : __ldg(&g_esrc[start + i]);
        float4 va = *(const float4*)(g_xl1 + (size_t)sa * 128 + 4 * l);
        gat_update_nc(va, xr4, at4, s0, c0);
    }
    float s = (s0 + s1) + (s2 + s3);
    float4 c;
    c.x = (c0.x + c1.x) + (c2.x + c3.x);
    c.y = (c0.y + c1.y) + (c2.y + c3.y);
    c.z = (c0.z + c1.z) + (c2.z + c3.z);
    c.w = (c0.w + c1.w) + (c2.w + c3.w);

    float inv = (cnt > 0) ? 1.f / s : 0.f;
    float4 b4 = *(const float4*)(bias + 4 * l);
    float4 o;
    o.x = c.x * inv + b4.x;
    o.y = c.y * inv + b4.y;
    o.z = c.z * inv + b4.z;
    o.w = c.w * inv + b4.w;
    o.x = o.x > 0.f ? o.x : (__expf(o.x) - 1.f);
    o.y = o.y > 0.f ? o.y : (__expf(o.y) - 1.f);
    o.z = o.z > 0.f ? o.z : (__expf(o.z) - 1.f);
    o.w = o.w > 0.f ? o.w : (__expf(o.w) - 1.f);
    *(float4*)(g_h + (size_t)node * 128 + 4 * l) = o;
}

// ---------------- Layer-2 linear: xl2/xr2 = h @ W2{l,r} + b2{l,r} ----------------
__global__ void lin2_kernel(const float* __restrict__ W2l, const float* __restrict__ b2l,
                            const float* __restrict__ W2r, const float* __restrict__ b2r, int n)
{
    __shared__ float wl[512], wr[512];
    int tx = threadIdx.x;
    for (int i = tx; i < 512; i += blockDim.x) { wl[i] = W2l[i]; wr[i] = W2r[i]; }
    __syncthreads();
    int node = (blockIdx.x * blockDim.x + tx) >> 5;
    if (node >= n) return;
    int l = tx & 31;
    float hv[4];
    *(float4*)hv = *(const float4*)(g_h + (size_t)node * 128 + 4 * l);
    float pl0 = 0.f, pl1 = 0.f, pl2 = 0.f, pl3 = 0.f;
    float pr0 = 0.f, pr1 = 0.f, pr2 = 0.f, pr3 = 0.f;
#pragma unroll
    for (int j = 0; j < 4; j++) {
        int k = 4 * l + j;
        float a = hv[j];
        pl0 += a * wl[k * 4 + 0]; pl1 += a * wl[k * 4 + 1];
        pl2 += a * wl[k * 4 + 2]; pl3 += a * wl[k * 4 + 3];
        pr0 += a * wr[k * 4 + 0]; pr1 += a * wr[k * 4 + 1];
        pr2 += a * wr[k * 4 + 2]; pr3 += a * wr[k * 4 + 3];
    }
#pragma unroll
    for (int off = 16; off; off >>= 1) {
        pl0 += __shfl_xor_sync(0xffffffffu, pl0, off);
        pl1 += __shfl_xor_sync(0xffffffffu, pl1, off);
        pl2 += __shfl_xor_sync(0xffffffffu, pl2, off);
        pl3 += __shfl_xor_sync(0xffffffffu, pl3, off);
        pr0 += __shfl_xor_sync(0xffffffffu, pr0, off);
        pr1 += __shfl_xor_sync(0xffffffffu, pr1, off);
        pr2 += __shfl_xor_sync(0xffffffffu, pr2, off);
        pr3 += __shfl_xor_sync(0xffffffffu, pr3, off);
    }
    if (l == 0) {
        float4 ol  = make_float4(pl0 + b2l[0], pl1 + b2l[1], pl2 + b2l[2], pl3 + b2l[3]);
        float4 orr = make_float4(pr0 + b2r[0], pr1 + b2r[1], pr2 + b2r[2], pr3 + b2r[3]);
        *(float4*)(g_xl2 + (size_t)node * 4) = ol;
        *(float4*)(g_xr2 + (size_t)node * 4) = orr;
    }
}

// ---------------- Layer-2 fused attention: TWO nodes per warp (16 lanes each) ----------------
__global__ void gat2_kernel(const float* __restrict__ att2, const float* __restrict__ bias2,
                            float* __restrict__ out, int n)
{
    int warp = (blockIdx.x * blockDim.x + threadIdx.x) >> 5;
    int l   = threadIdx.x & 31;
    int sub = l >> 4;           // which node in the pair
    int sl  = l & 15;           // lane within the 16-lane group
    int node_raw = warp * 2 + sub;
    if (warp * 2 >= n) return;
    int node = node_raw < n ? node_raw : n - 1;   // clamp (store predicated below)

    float xr[4]; *(float4*)xr = *(const float4*)(g_xr2 + (size_t)node * 4);
    float at[4]; *(float4*)at = *(const float4*)att2;
    float s = 0.f, a0 = 0.f, a1 = 0.f, a2 = 0.f, a3 = 0.f;
    int start = g_off[node];
    int cnt   = g_cnt[node];

    for (int i = sl; i < cnt; i += 16) {
        int src = __ldg(&g_esrc[start + i]);
        float v[4]; *(float4*)v = *(const float4*)(g_xl2 + (size_t)src * 4);
        float e0 = v[0] + xr[0]; e0 = e0 > 0.f ? e0 : 0.2f * e0;
        float e1 = v[1] + xr[1]; e1 = e1 > 0.f ? e1 : 0.2f * e1;
        float e2 = v[2] + xr[2]; e2 = e2 > 0.f ? e2 : 0.2f * e2;
        float e3 = v[3] + xr[3]; e3 = e3 > 0.f ? e3 : 0.2f * e3;
        float p = e0 * at[0] + e1 * at[1] + e2 * at[2] + e3 * at[3];
        float w = __expf(p);
        s  += w;
        a0 += w * v[0];
        a1 += w * v[1];
        a2 += w * v[2];
        a3 += w * v[3];
    }
    // merge within each 16-lane group (xor offsets never set bit 4)
#pragma unroll
    for (int off = 8; off; off >>= 1) {
        s  += __shfl_xor_sync(0xffffffffu, s, off);
        a0 += __shfl_xor_sync(0xffffffffu, a0, off);
        a1 += __shfl_xor_sync(0xffffffffu, a1, off);
        a2 += __shfl_xor_sync(0xffffffffu, a2, off);
        a3 += __shfl_xor_sync(0xffffffffu, a3, off);
    }
    if (sl == 0 && node_raw < n) {
        float inv = (cnt > 0) ? 1.f / s : 0.f;
        float4 o = make_float4(a0 * inv + bias2[0], a1 * inv + bias2[1],
                               a2 * inv + bias2[2], a3 * inv + bias2[3]);
        *(float4*)(out + (size_t)node * 4) = o;
    }
}

// ---------------- host launcher ----------------
extern "C" void kernel_launch(void* const* d_in, const int* in_sizes, int n_in,
                              void* d_out, int out_size)
{
    const float* x     = (const float*)d_in[0];
    const int*   ei    = (const int*)  d_in[1];
    const float* W1l   = (const float*)d_in[2];
    const float* b1l   = (const float*)d_in[3];
    const float* W1r   = (const float*)d_in[4];
    const float* b1r   = (const float*)d_in[5];
    const float* att1  = (const float*)d_in[6];
    const float* bias1 = (const float*)d_in[7];
    const float* W2l   = (const float*)d_in[8];
    const float* b2l   = (const float*)d_in[9];
    const float* W2r   = (const float*)d_in[10];
    const float* b2r   = (const float*)d_in[11];
    const float* att2  = (const float*)d_in[12];
    const float* bias2 = (const float*)d_in[13];
    float* out = (float*)d_out;

    int n = in_sizes[0] / 128;
    int e = in_sizes[1] / 2;
    const int* src = ei;
    const int* dst = ei + e;

    void *p_xl1, *p_xr1;
    cudaGetSymbolAddress(&p_xl1, g_xl1);
    cudaGetSymbolAddress(&p_xr1, g_xr1);

    static cudaStream_t s1 = nullptr;
    static cudaEvent_t ev_fork = nullptr, ev_join = nullptr;
    if (!s1) {
        cudaStreamCreateWithFlags(&s1, cudaStreamNonBlocking);
        cudaEventCreateWithFlags(&ev_fork, cudaEventDisableTiming);
        cudaEventCreateWithFlags(&ev_join, cudaEventDisableTiming);
    }

    // fork: CSR build on s1, GEMMs on the main (captured) stream
    cudaEventRecord(ev_fork, 0);
    cudaStreamWaitEvent(s1, ev_fork, 0);

    zero_kernel   <<<(n + 255) / 256, 256, 0, s1>>>(n);
    hist_kernel   <<<(e + 255) / 256, 256, 0, s1>>>(dst, e);
    scan_kernel   <<<1, 1024, 0, s1>>>(n);
    scatter_kernel<<<(e + 255) / 256, 256, 0, s1>>>(src, dst, e);
    cudaEventRecord(ev_join, s1);

    gemm_h2<<<(n + 127) / 128, 256>>>(x, W1l, b1l, (float*)p_xl1, n);
    gemm_h2<<<(n + 127) / 128, 256>>>(x, W1r, b1r, (float*)p_xr1, n);

    // join: gat1 needs both GEMM outputs and the CSR
    cudaStreamWaitEvent(0, ev_join, 0);

    gat1_kernel<<<(n + 7) / 8, 256>>>(att1, bias1, n);
    lin2_kernel<<<(n + 7) / 8, 256>>>(W2l, b2l, W2r, b2r, n);
    // two nodes per warp -> 16 nodes per 256-thread block
    gat2_kernel<<<(n + 15) / 16, 256>>>(att2, bias2, out, n);
}